// round 11
// baseline (speedup 1.0000x reference)
#include <cuda_runtime.h>
#include <cstddef>
#include <cstdint>

// CapsuleLayer dynamic routing, recompute-u_hat strategy + packed f32x2 math.
// x: [64, 2048, 8], W: [32, 2048, 16, 8], out v: [64, 32, 16] (fp32)
//
// Math restructure:
//   b starts at 0 and accumulates linearly => logits at iter k are u_hat . (v1+..+vk)
//   pass0: S1 = sum_n u_hat            (c uniform = 1/32 folded into squash)
//   pass1: c = softmax_j(u_hat . v1)        -> S2
//   pass2: c = softmax_j(u_hat . (v1+v2))   -> S3 -> v3 = output
//
// R11: fixes R10's pipeline race. With 4 buffers and 2 n/iter, prefetching
// stages 2it+4/2it+5 at iter top targets buffer (2it)&3 == the buffer being
// READ this iteration. New schedule: commit stages 2it+2/2it+3 (next iter's
// data) after wait_group 0 + syncthreads -> prefetch targets are buffers last
// read at iter it-1 (safe), compute buffers are disjoint (differ by 2 mod 4).
// Keeps: 2 n per barrier, fused inter-pass squash, 5 launches.

#define B_DIM 64
#define N_DIM 2048
#define I_DIM 8
#define J_DIM 32
#define D_DIM 16

#define NC 32              // n's per block
#define BC 8               // b's per block
#define WS_STRIDE 132      // floats per W row in smem (128 + 4 pad)
#define WBUF_FLOATS (J_DIM * WS_STRIDE)       // 4224 floats per stage
#define XT_FLOATS (BC * NC * I_DIM)           // 2048
#define TB_FLOATS (8 * J_DIM * 4)             // 1024 ([warp][j] float4)
#define SMEM_FLOATS (4 * WBUF_FLOATS + XT_FLOATS + TB_FLOATS)
#define SMEM_BYTES (SMEM_FLOATS * 4)          // 79872 B -> 2 CTAs/SM

__device__ float g_Wt[(size_t)J_DIM * N_DIM * 128];   // transposed W, [j][n][i][d]
__device__ float g_S[3][B_DIM * J_DIM * D_DIM];       // routing-pass accumulators

typedef unsigned long long ull;

__device__ __forceinline__ ull f2_fma(ull a, ull b, ull c) {
    ull d; asm("fma.rn.f32x2 %0, %1, %2, %3;" : "=l"(d) : "l"(a), "l"(b), "l"(c)); return d;
}
__device__ __forceinline__ ull f2_mul(ull a, ull b) {
    ull d; asm("mul.rn.f32x2 %0, %1, %2;" : "=l"(d) : "l"(a), "l"(b)); return d;
}
__device__ __forceinline__ ull f2_add(ull a, ull b) {
    ull d; asm("add.rn.f32x2 %0, %1, %2;" : "=l"(d) : "l"(a), "l"(b)); return d;
}
__device__ __forceinline__ ull f2_dup(float x) {
    ull d; asm("mov.b64 %0, {%1, %1};" : "=l"(d) : "f"(x)); return d;
}
__device__ __forceinline__ ull f2_pack(float lo, float hi) {
    ull d; asm("mov.b64 %0, {%1, %2};" : "=l"(d) : "f"(lo), "f"(hi)); return d;
}
__device__ __forceinline__ void f2_unpack(ull v, float& lo, float& hi) {
    asm("mov.b64 {%0, %1}, %2;" : "=f"(lo), "=f"(hi) : "l"(v));
}
__device__ __forceinline__ float f2_hsum(ull v) {
    float lo, hi; f2_unpack(v, lo, hi); return lo + hi;
}

__device__ __forceinline__ void cp16(void* dst_smem, const void* src) {
    uint32_t d = (uint32_t)__cvta_generic_to_shared(dst_smem);
    asm volatile("cp.async.cg.shared.global [%0], [%1], 16;" :: "r"(d), "l"(src));
}
__device__ __forceinline__ void cp_commit() { asm volatile("cp.async.commit_group;"); }
__device__ __forceinline__ void cp_wait0()  { asm volatile("cp.async.wait_group 0;"); }

// Transpose W[j][n][d][i] -> g_Wt[j][n][i][d], and zero g_S (replaces init kernel).
__global__ void transform_kernel(const float* __restrict__ W) {
    __shared__ float s[8][WS_STRIDE];
    const int t = threadIdx.x;
    const int gid = blockIdx.x * 256 + t;
    if (gid < 3 * B_DIM * J_DIM * D_DIM) ((float*)g_S)[gid] = 0.0f;

    const int r = t >> 5;
    const int l = t & 31;
    const size_t row = (size_t)blockIdx.x * 8 + r;

    const float4* src = reinterpret_cast<const float4*>(W + row * 128);
    *reinterpret_cast<float4*>(&s[r][l * 4]) = __ldg(src + l);
    __syncthreads();

    const int i = l >> 2, dq = l & 3;
    float4 o;
    o.x = s[r][(dq * 4 + 0) * I_DIM + i];
    o.y = s[r][(dq * 4 + 1) * I_DIM + i];
    o.z = s[r][(dq * 4 + 2) * I_DIM + i];
    o.w = s[r][(dq * 4 + 3) * I_DIM + i];
    *reinterpret_cast<float4*>(&g_Wt[row * 128 + l * 4]) = o;
}

// squash helper: given raw S row (4 float4s) and scale, return normalized quarter dq.
__device__ __forceinline__ float4 squash_quarter(const float4* Sp, float scale, int dq) {
    float4 r0 = Sp[0], r1 = Sp[1], r2 = Sp[2], r3 = Sp[3];
    r0.x *= scale; r0.y *= scale; r0.z *= scale; r0.w *= scale;
    r1.x *= scale; r1.y *= scale; r1.z *= scale; r1.w *= scale;
    r2.x *= scale; r2.y *= scale; r2.z *= scale; r2.w *= scale;
    r3.x *= scale; r3.y *= scale; r3.z *= scale; r3.w *= scale;
    float ssq = r0.x*r0.x + r0.y*r0.y + r0.z*r0.z + r0.w*r0.w
              + r1.x*r1.x + r1.y*r1.y + r1.z*r1.z + r1.w*r1.w
              + r2.x*r2.x + r2.y*r2.y + r2.z*r2.z + r2.w*r2.w
              + r3.x*r3.x + r3.y*r3.y + r3.z*r3.z + r3.w*r3.w;
    float inv = rsqrtf(ssq + 1e-7f);
    float4 q = (dq == 0) ? r0 : (dq == 1) ? r1 : (dq == 2) ? r2 : r3;
    q.x *= inv; q.y *= inv; q.z *= inv; q.w *= inv;
    return q;
}

// Block: 256 threads. lane = j (0..31). warp w: dq = w&3 (d-quarter), rep = w>>2.
// Each thread handles 4 b's (bbase + rep*4 + bs) x 4 d's (dq*4..dq*4+3) as f32x2 pairs.
// 4-stage cp.async pipeline on W, 2 n per barrier, distance-1 group schedule.
// For pass>=1 each block recomputes its V-slice from g_S (fused squash).
__global__ __launch_bounds__(256, 2) void pass_kernel(
    const float* __restrict__ x, int pass)
{
    extern __shared__ float smem[];
    float*  Wb    = smem;                          // 4 stages x 4224 floats
    float*  xtile = smem + 4 * WBUF_FLOATS;        // [b][nn][i] : 2048 floats
    float4* tbf   = reinterpret_cast<float4*>(xtile + XT_FLOATS); // [warp*32+j]

    const int t    = threadIdx.x;
    const int j    = t & 31;
    const int warp = t >> 5;
    const int dq   = warp & 3;              // d-quarter
    const int rep  = warp >> 2;             // 0..1

    const int bbase  = blockIdx.y * BC;
    const int n_base = blockIdx.x * NC;

    // W staging: thread stages row sj, chunks sp*4 + k*32 (conflict-free)
    const int sj = t >> 3;
    const int sp = t & 7;
    const float* wsrc_base = g_Wt + (size_t)sj * N_DIM * 128 + (size_t)n_base * 128 + sp * 4;
    float* wdst_base = Wb + sj * WS_STRIDE + sp * 4;

    // ---- prologue: one group = x tile + W stages 0,1 (iter 0's data) ----
    #pragma unroll
    for (int r = 0; r < 2; ++r) {
        int f = t + r * 256;
        int b_off = f >> 6;
        int rem   = f & 63;
        cp16(&xtile[b_off * (NC * I_DIM) + rem * 4],
             x + ((size_t)(bbase + b_off) * N_DIM + n_base) * I_DIM + rem * 4);
    }
    #pragma unroll
    for (int st = 0; st < 2; ++st)
        #pragma unroll
        for (int k = 0; k < 4; ++k)
            cp16(wdst_base + st * WBUF_FLOATS + k * 32,
                 wsrc_base + (size_t)st * 128 + k * 32);
    cp_commit();

    // ---- fused squash: recompute V-slice from g_S (overlaps cp.async) ----
    ull V2[4][2];
    if (pass != 0) {
        #pragma unroll
        for (int bs = 0; bs < 4; ++bs) {
            const size_t row = (size_t)(bbase + rep * 4 + bs) * J_DIM + j;
            float4 q = squash_quarter(
                reinterpret_cast<const float4*>(&g_S[0][row * D_DIM]),
                1.0f / 32.0f, dq);
            if (pass == 2) {
                float4 q2 = squash_quarter(
                    reinterpret_cast<const float4*>(&g_S[1][row * D_DIM]),
                    1.0f, dq);
                q.x += q2.x; q.y += q2.y; q.z += q2.z; q.w += q2.w;
            }
            V2[bs][0] = f2_pack(q.x, q.y);
            V2[bs][1] = f2_pack(q.z, q.w);
        }
    }

    ull acc2[4][2];
    #pragma unroll
    for (int bs = 0; bs < 4; ++bs) { acc2[bs][0] = 0ull; acc2[bs][1] = 0ull; }

    // 16 iterations, 2 n each. At iter it: wait all -> sync -> commit stages
    // 2it+2, 2it+3 (next iter; target buffers were read at iter it-1) -> compute.
    for (int it = 0; it < NC / 2; ++it) {
        cp_wait0();          // everything committed so far has landed
        __syncthreads();     // all warps done reading the buffers being refilled

        if (2 * it + 2 < NC) {
            #pragma unroll
            for (int h = 0; h < 2; ++h) {
                const int st = 2 * it + 2 + h;
                float* dst = wdst_base + (st & 3) * WBUF_FLOATS;
                const float* src = wsrc_base + (size_t)st * 128;
                #pragma unroll
                for (int k = 0; k < 4; ++k) cp16(dst + k * 32, src + k * 32);
            }
        }
        cp_commit();

        #pragma unroll
        for (int h = 0; h < 2; ++h) {
            const int nn = 2 * it + h;

            // x for 4 b's (broadcast smem reads)
            float xs[4][8];
            #pragma unroll
            for (int bs = 0; bs < 4; ++bs) {
                const float4* xp = reinterpret_cast<const float4*>(
                    &xtile[(rep * 4 + bs) * (NC * I_DIM) + nn * I_DIM]);
                float4 a = xp[0], b = xp[1];
                xs[bs][0] = a.x; xs[bs][1] = a.y; xs[bs][2] = a.z; xs[bs][3] = a.w;
                xs[bs][4] = b.x; xs[bs][5] = b.y; xs[bs][6] = b.z; xs[bs][7] = b.w;
            }

            // u_hat (packed d-pairs): stage layout [i][d], quarter = dq*4..dq*4+3
            const float* Wc = Wb + (nn & 3) * WBUF_FLOATS + j * WS_STRIDE + dq * 4;
            ull u2[4][2];
            {
                ulonglong2 wv = *reinterpret_cast<const ulonglong2*>(Wc);
                #pragma unroll
                for (int bs = 0; bs < 4; ++bs) {
                    ull xd = f2_dup(xs[bs][0]);
                    u2[bs][0] = f2_mul(wv.x, xd);
                    u2[bs][1] = f2_mul(wv.y, xd);
                }
            }
            #pragma unroll
            for (int i = 1; i < 8; ++i) {
                ulonglong2 wv = *reinterpret_cast<const ulonglong2*>(Wc + i * 16);
                #pragma unroll
                for (int bs = 0; bs < 4; ++bs) {
                    ull xd = f2_dup(xs[bs][i]);
                    u2[bs][0] = f2_fma(wv.x, xd, u2[bs][0]);
                    u2[bs][1] = f2_fma(wv.y, xd, u2[bs][1]);
                }
            }

            if (pass != 0) {
                // logit partials over this d-quarter, packed exchange (one STS.128)
                float4 part;
                part.x = f2_hsum(f2_fma(u2[0][0], V2[0][0], f2_mul(u2[0][1], V2[0][1])));
                part.y = f2_hsum(f2_fma(u2[1][0], V2[1][0], f2_mul(u2[1][1], V2[1][1])));
                part.z = f2_hsum(f2_fma(u2[2][0], V2[2][0], f2_mul(u2[2][1], V2[2][1])));
                part.w = f2_hsum(f2_fma(u2[3][0], V2[3][0], f2_mul(u2[3][1], V2[3][1])));
                tbf[warp * 32 + j] = part;
                asm volatile("bar.sync %0, 128;" :: "r"(1 + rep) : "memory");
                const int wg = rep * 4;
                float4 a0 = tbf[(wg + 0) * 32 + j];
                float4 a1 = tbf[(wg + 1) * 32 + j];
                float4 a2 = tbf[(wg + 2) * 32 + j];
                float4 a3 = tbf[(wg + 3) * 32 + j];
                // logits are O(1): softmax without max-subtraction is safe here
                float e0 = __expf((a0.x + a1.x) + (a2.x + a3.x));
                float e1 = __expf((a0.y + a1.y) + (a2.y + a3.y));
                float e2 = __expf((a0.z + a1.z) + (a2.z + a3.z));
                float e3 = __expf((a0.w + a1.w) + (a2.w + a3.w));
                // 4 interleaved butterflies: independent chains pipeline
                float z0 = e0, z1 = e1, z2 = e2, z3 = e3;
                #pragma unroll
                for (int o = 16; o; o >>= 1) {
                    z0 += __shfl_xor_sync(0xffffffffu, z0, o);
                    z1 += __shfl_xor_sync(0xffffffffu, z1, o);
                    z2 += __shfl_xor_sync(0xffffffffu, z2, o);
                    z3 += __shfl_xor_sync(0xffffffffu, z3, o);
                }
                ull c2;
                c2 = f2_dup(__fdividef(e0, z0));
                acc2[0][0] = f2_fma(c2, u2[0][0], acc2[0][0]);
                acc2[0][1] = f2_fma(c2, u2[0][1], acc2[0][1]);
                c2 = f2_dup(__fdividef(e1, z1));
                acc2[1][0] = f2_fma(c2, u2[1][0], acc2[1][0]);
                acc2[1][1] = f2_fma(c2, u2[1][1], acc2[1][1]);
                c2 = f2_dup(__fdividef(e2, z2));
                acc2[2][0] = f2_fma(c2, u2[2][0], acc2[2][0]);
                acc2[2][1] = f2_fma(c2, u2[2][1], acc2[2][1]);
                c2 = f2_dup(__fdividef(e3, z3));
                acc2[3][0] = f2_fma(c2, u2[3][0], acc2[3][0]);
                acc2[3][1] = f2_fma(c2, u2[3][1], acc2[3][1]);
            } else {
                #pragma unroll
                for (int bs = 0; bs < 4; ++bs) {
                    acc2[bs][0] = f2_add(acc2[bs][0], u2[bs][0]);
                    acc2[bs][1] = f2_add(acc2[bs][1], u2[bs][1]);
                }
            }
        }
    }

    float* S = g_S[pass];
    #pragma unroll
    for (int bs = 0; bs < 4; ++bs) {
        float* dst = &S[((size_t)(bbase + rep * 4 + bs) * J_DIM + j) * D_DIM + dq * 4];
        float a, b, c, d;
        f2_unpack(acc2[bs][0], a, b);
        f2_unpack(acc2[bs][1], c, d);
        atomicAdd(dst + 0, a);
        atomicAdd(dst + 1, b);
        atomicAdd(dst + 2, c);
        atomicAdd(dst + 3, d);
    }
}

// final squash only: out = squash(S2). idx = (b*32 + j).
__global__ void squash_final_kernel(float* __restrict__ out) {
    int idx = blockIdx.x * blockDim.x + threadIdx.x;
    if (idx >= B_DIM * J_DIM) return;
    const float* S = g_S[2];
    float s[D_DIM];
    float ssq = 0.0f;
#pragma unroll
    for (int d = 0; d < D_DIM; ++d) {
        float v = S[idx * D_DIM + d];
        s[d] = v;
        ssq = fmaf(v, v, ssq);
    }
    float inv = rsqrtf(ssq + 1e-7f);
#pragma unroll
    for (int d = 0; d < D_DIM; ++d) out[idx * D_DIM + d] = s[d] * inv;
}

extern "C" void kernel_launch(void* const* d_in, const int* in_sizes, int n_in,
                              void* d_out, int out_size) {
    const float* x = (const float*)d_in[0];
    const float* W = (const float*)d_in[1];
    // robust to input ordering: x has 64*2048*8 = 1048576 elements
    if (in_sizes[0] != B_DIM * N_DIM * I_DIM) {
        x = (const float*)d_in[1];
        W = (const float*)d_in[0];
    }
    float* out = (float*)d_out;

    cudaFuncSetAttribute(pass_kernel,
                         cudaFuncAttributeMaxDynamicSharedMemorySize, SMEM_BYTES);

    dim3 grid(N_DIM / NC, B_DIM / BC);   // (64, 8) = 512 blocks (work-stealing slack)

    transform_kernel<<<(J_DIM * N_DIM) / 8, 256>>>(W);   // also zeroes g_S
    pass_kernel<<<grid, 256, SMEM_BYTES>>>(x, 0);
    pass_kernel<<<grid, 256, SMEM_BYTES>>>(x, 1);        // squash(S0) fused in prologue
    pass_kernel<<<grid, 256, SMEM_BYTES>>>(x, 2);        // squash(S0)+squash(S1) fused
    squash_final_kernel<<<8, 256>>>(out);
}